// round 8
// baseline (speedup 1.0000x reference)
#include <cuda_runtime.h>
#include <cuda_bf16.h>
#include <math.h>
#include <stdint.h>

// Problem constants
#define BQ      1024
#define DIM     256
#define NTRAIN  200000
#define NCLASS  1000
#define KSEL    20
#define KCAND   64          // int8 candidates kept for exact fp32 rescoring
#define TEMPF   20.0f
#define EPSF    1e-8f

// Tiling
#define CHUNK    2048
#define NCHUNKS  98
#define NPAD     (NCHUNKS*CHUNK)     // 200704 padded train rows
#define QTILES   8
#define NCANDTOT (NCHUNKS*KSEL)      // 1960 candidates/query
#define TILES_PC 16                  // 128-row tiles per chunk

// knn_main dynamic smem layout (bytes). int8: 256B per row (full K).
#define OFF_A    0u                  // 128 x 256B = 32768
#define OFF_B0   32768u
#define OFF_B1   65536u
#define OFF_SIMS 98304u              // 128 x 130 fp32 = 66560
#define OFF_TOPV 164864u             // 128 x 21 fp32 = 10752
#define OFF_TOPI 175616u
#define OFF_TV   186368u             // 128 fp32 = 512
#define SMEM_TOT 186880u
#define SIMS_PITCH 130

// Scratch (__device__ globals; no allocations allowed)
__device__ float   g_qn[BQ * DIM];             // fp32 normalized queries (rescore)
__device__ int8_t  g_qi8[BQ * DIM];            // int8 quantized normalized queries
__device__ int8_t  g_ti8[(size_t)NPAD * DIM];  // int8 quantized normalized train bank
__device__ float   g_st [NPAD];                // per-row dequant scale (maxabs/127)
__device__ float   g_tinv[NPAD];               // 1/max(||t||,eps)  (exact rescore)
__device__ float g_pvals[(size_t)BQ * NCHUNKS * KSEL];
__device__ int   g_pidx [(size_t)BQ * NCHUNKS * KSEL];

// ---------------------------------------------------------------------------
// Plain-PTX helpers (valid on base sm_103 target)
// ---------------------------------------------------------------------------
__device__ __forceinline__ uint32_t smem_u32(const void* p) {
    uint32_t a;
    asm("{ .reg .u64 t; cvta.to.shared.u64 t, %1; cvt.u32.u64 %0, t; }"
        : "=r"(a) : "l"(p));
    return a;
}
__device__ __forceinline__ void cp16(uint32_t dst, const void* src) {
    asm volatile("cp.async.cg.shared.global [%0], [%1], 16;"
                 :: "r"(dst), "l"(src));
}
#define CP_COMMIT() asm volatile("cp.async.commit_group;" ::: "memory")
#define CP_WAIT1()  asm volatile("cp.async.wait_group 1;" ::: "memory")

__device__ __forceinline__ void ldsm_x4(uint32_t addr, uint32_t& r0, uint32_t& r1,
                                        uint32_t& r2, uint32_t& r3) {
    asm volatile("ldmatrix.sync.aligned.m8n8.x4.shared.b16 {%0,%1,%2,%3}, [%4];"
                 : "=r"(r0), "=r"(r1), "=r"(r2), "=r"(r3) : "r"(addr));
}
// int8 MMA: m16n8k32, s32 accumulate (exact)
__device__ __forceinline__ void imma16832(int* d, const uint32_t* a,
                                          uint32_t b0, uint32_t b1) {
    asm volatile("mma.sync.aligned.m16n8k32.row.col.s32.s8.s8.s32 "
                 "{%0,%1,%2,%3}, {%4,%5,%6,%7}, {%8,%9}, {%0,%1,%2,%3};"
                 : "+r"(d[0]), "+r"(d[1]), "+r"(d[2]), "+r"(d[3])
                 : "r"(a[0]), "r"(a[1]), "r"(a[2]), "r"(a[3]), "r"(b0), "r"(b1));
}

// ---------------------------------------------------------------------------
// Kernel 1: q = normalize((x-mean)*inv_std) -> fp32 (rescore) + int8 (MMA A)
// ---------------------------------------------------------------------------
__global__ void qnorm_kernel(const float* __restrict__ x,
                             const float* __restrict__ mean,
                             const float* __restrict__ inv_std) {
    int b = blockIdx.x;
    int d = threadIdx.x;            // blockDim = 256 = DIM
    float v = (x[b * DIM + d] - mean[d]) * inv_std[d];
    float s = v * v;
    #pragma unroll
    for (int o = 16; o; o >>= 1) s += __shfl_xor_sync(0xffffffffu, s, o);
    __shared__ float ws[8];
    int w = threadIdx.x >> 5, l = threadIdx.x & 31;
    if (l == 0) ws[w] = s;
    __syncthreads();
    if (threadIdx.x == 0) {
        float t = 0.f;
        #pragma unroll
        for (int i = 0; i < 8; i++) t += ws[i];
        ws[0] = t;
    }
    __syncthreads();
    float outv = v / fmaxf(sqrtf(ws[0]), EPSF);
    g_qn[b * DIM + d] = outv;
    __syncthreads();                        // all reads of ws[0] done
    // block max |outv| for per-query int8 scale (scale is ranking-invariant)
    float ma = fabsf(outv);
    #pragma unroll
    for (int o = 16; o; o >>= 1) ma = fmaxf(ma, __shfl_xor_sync(0xffffffffu, ma, o));
    if (l == 0) ws[w] = ma;
    __syncthreads();
    if (threadIdx.x == 0) {
        float t = ws[0];
        #pragma unroll
        for (int i = 1; i < 8; i++) t = fmaxf(t, ws[i]);
        ws[0] = fmaxf(t, 1e-20f);
    }
    __syncthreads();
    float sc = 127.f / ws[0];
    int qv = __float2int_rn(outv * sc);
    qv = max(-127, min(127, qv));
    g_qi8[b * DIM + d] = (int8_t)qv;
}

// ---------------------------------------------------------------------------
// Kernel 2: int8 normalized train bank + per-row scales + fp32 inv norms
//   one warp per row
// ---------------------------------------------------------------------------
__global__ void tconv_kernel(const float* __restrict__ tx) {
    int gw   = (blockIdx.x * blockDim.x + threadIdx.x) >> 5;
    int lane = threadIdx.x & 31;
    if (gw >= NPAD) return;
    uint2* dst = (uint2*)(g_ti8 + (size_t)gw * DIM) + lane;   // 8 int8 per lane
    if (gw >= NTRAIN) {
        uint2 z; z.x = z.y = 0u;
        *dst = z;
        if (lane == 0) { g_tinv[gw] = 0.f; g_st[gw] = 0.f; }
        return;
    }
    const float4* row = (const float4*)(tx + (size_t)gw * DIM);
    float4 a = row[lane * 2];
    float4 b = row[lane * 2 + 1];
    float s = a.x*a.x + a.y*a.y + a.z*a.z + a.w*a.w
            + b.x*b.x + b.y*b.y + b.z*b.z + b.w*b.w;
    #pragma unroll
    for (int o = 16; o; o >>= 1) s += __shfl_xor_sync(0xffffffffu, s, o);
    float inv = 1.f / fmaxf(sqrtf(s), EPSF);
    float tn[8];
    tn[0]=a.x*inv; tn[1]=a.y*inv; tn[2]=a.z*inv; tn[3]=a.w*inv;
    tn[4]=b.x*inv; tn[5]=b.y*inv; tn[6]=b.z*inv; tn[7]=b.w*inv;
    float ma = 0.f;
    #pragma unroll
    for (int i = 0; i < 8; i++) ma = fmaxf(ma, fabsf(tn[i]));
    #pragma unroll
    for (int o = 16; o; o >>= 1) ma = fmaxf(ma, __shfl_xor_sync(0xffffffffu, ma, o));
    ma = fmaxf(ma, 1e-20f);
    float sc = 127.f / ma;
    uint32_t p[2] = {0u, 0u};
    #pragma unroll
    for (int i = 0; i < 8; i++) {
        int qv = __float2int_rn(tn[i] * sc);
        qv = max(-127, min(127, qv));
        p[i >> 2] |= ((uint32_t)qv & 0xFFu) << ((i & 3) * 8);
    }
    uint2 o2; o2.x = p[0]; o2.y = p[1];
    *dst = o2;
    if (lane == 0) { g_tinv[gw] = inv; g_st[gw] = ma / 127.f; }
}

// ---------------------------------------------------------------------------
// 32KB tile loader: 128 rows x 256B (full K as int8), xor-swizzled, cp.async
// ---------------------------------------------------------------------------
__device__ __forceinline__ void load_tile(uint32_t smdst,
                                          const int8_t* src_base, int tid) {
    #pragma unroll
    for (int k = 0; k < 8; k++) {
        int l = tid + k * 256;
        int row = l >> 4, c = l & 15;
        uint32_t dst = smdst + (uint32_t)row * 256u
                     + (uint32_t)((c ^ (row & 7)) * 16);
        cp16(dst, src_base + (size_t)row * DIM + c * 16);
    }
}

// ---------------------------------------------------------------------------
// Kernel 3: int8 warp-MMA GEMM (128x128xK256 per tile) + fused per-chunk top-20
//   grid = (NCHUNKS, QTILES), block = 256 (8 warps, 2M x 4N), 1 CTA/SM
// ---------------------------------------------------------------------------
__global__ __launch_bounds__(256, 1)
void knn_main() {
    extern __shared__ char sm[];
    uint32_t smb = smem_u32(sm);
    const int tid  = threadIdx.x;
    const int wid  = tid >> 5, lane = tid & 31;
    const int wm = wid >> 2, wn = wid & 3;          // warp grid 2 x 4
    const int qtile = blockIdx.y, chunk = blockIdx.x;
    const int tbase0 = chunk * CHUNK;

    float* sims = (float*)(sm + OFF_SIMS);
    float* topv = (float*)(sm + OFF_TOPV);
    int*   topi = (int*)  (sm + OFF_TOPI);
    float* tv   = (float*)(sm + OFF_TV);

    for (int l = tid; l < 128 * KSEL; l += 256)
        topv[(l / KSEL) * 21 + (l % KSEL)] = -1e30f;

    // Prologue: A tile (queries) + B tile 0 in group 0; B tile 1 in group 1
    load_tile(smb + OFF_A,  g_qi8 + (size_t)qtile * 128 * DIM, tid);
    load_tile(smb + OFF_B0, g_ti8 + (size_t)tbase0 * DIM, tid);
    CP_COMMIT();
    load_tile(smb + OFF_B1, g_ti8 + (size_t)(tbase0 + 128) * DIM, tid);
    CP_COMMIT();

    // per-thread fragment row bases (identical addressing to bf16 path:
    // 16x32 s8 tile has the same byte layout as 16x16 b16)
    int aRow[4], bRow[2];
    #pragma unroll
    for (int i = 0; i < 4; i++) aRow[i] = wm * 64 + i * 16 + (lane & 15);
    #pragma unroll
    for (int j2 = 0; j2 < 2; j2++)
        bRow[j2] = wn * 32 + j2 * 16 + (lane & 7) + ((lane & 16) >> 1);
    const int aHalf = lane >> 4;
    const int bHalf = (lane >> 3) & 1;

    float minv = -1e30f; int minp = 0;

    for (int t = 0; t < TILES_PC; t++) {
        int tbase = tbase0 + t * 128;
        CP_WAIT1();                          // B tile t resident
        if (tid >= 128) tv[tid - 128] = g_st[tbase + tid - 128];
        __syncthreads();

        int acc[4][4][4];
        #pragma unroll
        for (int i = 0; i < 4; i++)
            #pragma unroll
            for (int j = 0; j < 4; j++)
                #pragma unroll
                for (int e = 0; e < 4; e++) acc[i][j][e] = 0;

        uint32_t bbase = smb + (t & 1 ? OFF_B1 : OFF_B0);
        #pragma unroll
        for (int kk = 0; kk < 8; kk++) {     // K=256, 32 per step
            uint32_t a[4][4];
            int cA = kk * 2 + aHalf;
            #pragma unroll
            for (int i = 0; i < 4; i++) {
                uint32_t ad = smb + OFF_A + (uint32_t)aRow[i] * 256u
                            + (uint32_t)(((cA ^ (aRow[i] & 7))) * 16);
                ldsm_x4(ad, a[i][0], a[i][1], a[i][2], a[i][3]);
            }
            uint32_t b[2][4];
            int cB = kk * 2 + bHalf;
            #pragma unroll
            for (int j2 = 0; j2 < 2; j2++) {
                uint32_t bd = bbase + (uint32_t)bRow[j2] * 256u
                            + (uint32_t)(((cB ^ (bRow[j2] & 7))) * 16);
                ldsm_x4(bd, b[j2][0], b[j2][1], b[j2][2], b[j2][3]);
            }
            #pragma unroll
            for (int i = 0; i < 4; i++)
                #pragma unroll
                for (int j = 0; j < 4; j++)
                    imma16832(acc[i][j], a[i],
                              b[j >> 1][(j & 1) * 2], b[j >> 1][(j & 1) * 2 + 1]);
        }
        __syncthreads();                     // all warps done reading B buf

        // prefetch B tile t+2 (same buffer) then commit (keep group count aligned)
        if (t + 2 < TILES_PC)
            load_tile(bbase, g_ti8 + (size_t)(tbase0 + (t + 2) * 128) * DIM, tid);
        CP_COMMIT();

        // stage scaled sims
        float tvr[4][2];
        #pragma unroll
        for (int j = 0; j < 4; j++) {
            int c0 = wn * 32 + j * 8 + 2 * (lane & 3);
            tvr[j][0] = tv[c0]; tvr[j][1] = tv[c0 + 1];
        }
        #pragma unroll
        for (int i = 0; i < 4; i++) {
            int r0 = wm * 64 + i * 16 + (lane >> 2);
            #pragma unroll
            for (int j = 0; j < 4; j++) {
                int c0 = wn * 32 + j * 8 + 2 * (lane & 3);
                *(float2*)&sims[r0 * SIMS_PITCH + c0] =
                    make_float2((float)acc[i][j][0] * tvr[j][0],
                                (float)acc[i][j][1] * tvr[j][1]);
                *(float2*)&sims[(r0 + 8) * SIMS_PITCH + c0] =
                    make_float2((float)acc[i][j][2] * tvr[j][0],
                                (float)acc[i][j][3] * tvr[j][1]);
            }
        }
        __syncthreads();

        // per-query top-20 scan (one thread per query)
        if (tid < 128) {
            int lim = min(128, NTRAIN - tbase);
            const float* srow = sims + tid * SIMS_PITCH;
            float* tvq = topv + tid * 21;
            int*   tiq = topi + tid * 21;
            for (int j = 0; j < lim; j++) {
                float v = srow[j];
                if (v > minv) {
                    tvq[minp] = v; tiq[minp] = tbase + j;
                    minv = tvq[0]; minp = 0;
                    #pragma unroll
                    for (int m = 1; m < KSEL; m++) {
                        float t2 = tvq[m];
                        if (t2 < minv) { minv = t2; minp = m; }
                    }
                }
            }
        }
        __syncthreads();
    }

    if (tid < 128) {
        int q = qtile * 128 + tid;
        size_t base = ((size_t)q * NCHUNKS + chunk) * KSEL;
        #pragma unroll
        for (int j = 0; j < KSEL; j++) {
            g_pvals[base + j] = topv[tid * 21 + j];
            g_pidx [base + j] = topi[tid * 21 + j];
        }
    }
}

// ---------------------------------------------------------------------------
// Kernel 4: top-64 int8 candidates -> exact fp32 rescore -> top-20 -> softmax
//   grid = BQ, block = 256
// ---------------------------------------------------------------------------
__global__ __launch_bounds__(256)
void knn_merge(const float* __restrict__ train, const void* __restrict__ ty_raw,
               float* __restrict__ out) {
    __shared__ float vals[NCANDTOT];
    __shared__ int   idxs[NCANDTOT];
    __shared__ __align__(16) float qs[DIM];
    __shared__ int   seli[KCAND];
    __shared__ float rsc[KCAND];
    __shared__ float s2v[KSEL];
    __shared__ int   s2i[KSEL];
    __shared__ float rv[8];
    __shared__ int   rp[8];

    int q = blockIdx.x, tid = threadIdx.x;
    for (int l = tid; l < NCANDTOT; l += 256) {
        vals[l] = g_pvals[(size_t)q * NCANDTOT + l];
        idxs[l] = g_pidx [(size_t)q * NCANDTOT + l];
    }
    qs[tid] = g_qn[(size_t)q * DIM + tid];
    for (int c = tid; c < NCLASS; c += 256) out[(size_t)q * NCLASS + c] = 0.f;
    __syncthreads();

    // register-local maxima: thread owns candidates tid + k*256
    float lmax = -INFINITY; int lpos = tid;
    for (int l = tid; l < NCANDTOT; l += 256) {
        float v = vals[l];
        if (v > lmax) { lmax = v; lpos = l; }
    }

    // iterative top-KCAND selection (winner-only rescan)
    for (int it = 0; it < KCAND; it++) {
        float bv = lmax; int bt = tid;
        #pragma unroll
        for (int o = 16; o; o >>= 1) {
            float ov = __shfl_xor_sync(0xffffffffu, bv, o);
            int   ot = __shfl_xor_sync(0xffffffffu, bt, o);
            if (ov > bv || (ov == bv && ot < bt)) { bv = ov; bt = ot; }
        }
        if ((tid & 31) == 0) { rv[tid >> 5] = bv; rp[tid >> 5] = bt; }
        __syncthreads();
        float fb = rv[0]; int ft = rp[0];
        #pragma unroll
        for (int i = 1; i < 8; i++)
            if (rv[i] > fb || (rv[i] == fb && rp[i] < ft)) { fb = rv[i]; ft = rp[i]; }
        if (tid == ft) {
            seli[it] = idxs[lpos];
            vals[lpos] = -INFINITY;
            lmax = -INFINITY; lpos = tid;
            for (int l = tid; l < NCANDTOT; l += 256) {
                float v = vals[l];
                if (v > lmax) { lmax = v; lpos = l; }
            }
        }
        __syncthreads();
    }

    // exact fp32 rescore: 4 threads per candidate, 64 dims each
    {
        int c = tid >> 2, seg = tid & 3;
        const float4* tr = (const float4*)(train + (size_t)seli[c] * DIM + seg * 64);
        const float4* qq = (const float4*)(qs + seg * 64);
        float s = 0.f;
        #pragma unroll
        for (int i = 0; i < 16; i++) {
            float4 tvv = tr[i]; float4 qv = qq[i];
            s += tvv.x * qv.x + tvv.y * qv.y + tvv.z * qv.z + tvv.w * qv.w;
        }
        s += __shfl_down_sync(0xffffffffu, s, 2, 4);
        s += __shfl_down_sync(0xffffffffu, s, 1, 4);
        if (seg == 0) rsc[c] = s * g_tinv[seli[c]];
    }
    __syncthreads();

    // exact top-20 of 64 rescored candidates (warp 0; tie-break lower train idx)
    if (tid < 32) {
        float m0 = rsc[tid],  m1 = rsc[tid + 32];
        int   i0 = seli[tid], i1 = seli[tid + 32];
        for (int it = 0; it < KSEL; it++) {
            bool s0 = (m0 > m1) || (m0 == m1 && i0 < i1);
            float lv = s0 ? m0 : m1;
            int   li = s0 ? i0 : i1;
            int   lp = s0 ? tid : tid + 32;
            #pragma unroll
            for (int o = 16; o; o >>= 1) {
                float ov = __shfl_xor_sync(0xffffffffu, lv, o);
                int   oi = __shfl_xor_sync(0xffffffffu, li, o);
                int   op = __shfl_xor_sync(0xffffffffu, lp, o);
                if (ov > lv || (ov == lv && oi < li)) { lv = ov; li = oi; lp = op; }
            }
            if (tid == 0) { s2v[it] = lv; s2i[it] = li; }
            if (tid == (lp & 31)) { if (lp >= 32) m1 = -INFINITY; else m0 = -INFINITY; }
        }
        __syncwarp();
    }
    __syncthreads();

    if (tid == 0) {
        // detect int64 vs int32 labels (labels < 1000 -> zero high words)
        const int* y32 = (const int*)ty_raw;
        bool is64 = true;
        #pragma unroll
        for (int i = 1; i < 32; i += 2) is64 = is64 && (y32[i] == 0);

        float m0 = s2v[0], s = 0.f;
        float w20[KSEL];
        #pragma unroll
        for (int j = 0; j < KSEL; j++) {
            float w = expf((s2v[j] - m0) * TEMPF);
            w20[j] = w; s += w;
        }
        float inv = 1.f / s;
        for (int j = 0; j < KSEL; j++) {
            int id  = s2i[j];
            int lab = is64 ? (int)((const long long*)ty_raw)[id] : y32[id];
            out[(size_t)q * NCLASS + lab] += w20[j] * inv;
        }
    }
}

// ---------------------------------------------------------------------------
extern "C" void kernel_launch(void* const* d_in, const int* in_sizes, int n_in,
                              void* d_out, int out_size) {
    const float* x       = (const float*)d_in[0];
    const float* mean    = (const float*)d_in[1];
    const float* inv_std = (const float*)d_in[2];
    const float* train_x = (const float*)d_in[3];
    const void*  train_y = d_in[4];
    float* out = (float*)d_out;

    qnorm_kernel<<<BQ, 256>>>(x, mean, inv_std);
    tconv_kernel<<<NPAD / 8, 256>>>(train_x);          // 1 warp per row

    cudaFuncSetAttribute(knn_main, cudaFuncAttributeMaxDynamicSharedMemorySize, SMEM_TOT);
    knn_main<<<dim3(NCHUNKS, QTILES), 256, SMEM_TOT>>>();

    knn_merge<<<BQ, 256>>>(train_x, train_y, out);
}

// round 13
// speedup vs baseline: 1.4214x; 1.4214x over previous
#include <cuda_runtime.h>
#include <cuda_bf16.h>
#include <math.h>
#include <stdint.h>

// Problem constants
#define BQ      1024
#define DIM     256
#define NTRAIN  200000
#define NCLASS  1000
#define KSEL    20
#define KCAND   32          // bf16 candidates kept for fp32 rescoring
#define TEMPF   20.0f
#define EPSF    1e-8f

// Tiling
#define CHUNK    2048
#define NCHUNKS  98
#define NPAD     (NCHUNKS*CHUNK)     // 200704 padded train rows
#define QTILES   8
#define NCANDTOT (NCHUNKS*KSEL)      // 1960 candidates/query
#define TILES_PC 16                  // 128-row tiles per chunk
#define NSLABS   32                  // 2 K-slabs per tile
#define NTHREADS 512

// knn_main dynamic smem layout (bytes)
#define OFF_A    0u                  // A: 128 rows x 512B (256 bf16)   = 65536
#define OFF_B0   65536u              // B slab: 128 rows x 256B (128 bf16) = 32768
#define OFF_B1   98304u
#define OFF_SIMS 131072u             // 128 x 130 fp32 = 66560
#define OFF_TOPV 197632u             // 128 x 21 fp32  = 10752
#define OFF_TOPI 208384u             // 128 x 21 int   = 10752
#define SMEM_TOT 219136u
#define SIMS_PITCH 130

// Scratch (__device__ globals; no allocations allowed)
__device__ float          g_qn[BQ * DIM];            // fp32 normalized queries
__device__ __nv_bfloat16  g_qb[BQ * DIM];            // bf16 normalized queries
__device__ __nv_bfloat16  g_tb[(size_t)NPAD * DIM];  // bf16 pre-normalized train bank
__device__ float          g_tinv[NPAD];              // 1/max(||t||,eps)
__device__ float g_pvals[(size_t)BQ * NCHUNKS * KSEL];
__device__ int   g_pidx [(size_t)BQ * NCHUNKS * KSEL];

// ---------------------------------------------------------------------------
// Plain-PTX helpers (valid on base sm_103 target: no "a"-only features)
// ---------------------------------------------------------------------------
__device__ __forceinline__ uint32_t smem_u32(const void* p) {
    uint32_t a;
    asm("{ .reg .u64 t; cvta.to.shared.u64 t, %1; cvt.u32.u64 %0, t; }"
        : "=r"(a) : "l"(p));
    return a;
}
__device__ __forceinline__ void cp16(uint32_t dst, const void* src) {
    asm volatile("cp.async.cg.shared.global [%0], [%1], 16;"
                 :: "r"(dst), "l"(src));
}
#define CP_COMMIT() asm volatile("cp.async.commit_group;" ::: "memory")
#define CP_WAIT1()  asm volatile("cp.async.wait_group 1;" ::: "memory")

__device__ __forceinline__ void ldsm_x4(uint32_t addr, uint32_t& r0, uint32_t& r1,
                                        uint32_t& r2, uint32_t& r3) {
    asm volatile("ldmatrix.sync.aligned.m8n8.x4.shared.b16 {%0,%1,%2,%3}, [%4];"
                 : "=r"(r0), "=r"(r1), "=r"(r2), "=r"(r3) : "r"(addr));
}
__device__ __forceinline__ void mma16816(float* d, const uint32_t* a,
                                         uint32_t b0, uint32_t b1) {
    asm volatile("mma.sync.aligned.m16n8k16.row.col.f32.bf16.bf16.f32 "
                 "{%0,%1,%2,%3}, {%4,%5,%6,%7}, {%8,%9}, {%0,%1,%2,%3};"
                 : "+f"(d[0]), "+f"(d[1]), "+f"(d[2]), "+f"(d[3])
                 : "r"(a[0]), "r"(a[1]), "r"(a[2]), "r"(a[3]), "r"(b0), "r"(b1));
}

// ---------------------------------------------------------------------------
// Kernel 1: q = normalize((x - mean) * inv_std)  -> fp32 + bf16
// ---------------------------------------------------------------------------
__global__ void qnorm_kernel(const float* __restrict__ x,
                             const float* __restrict__ mean,
                             const float* __restrict__ inv_std) {
    int b = blockIdx.x;
    int d = threadIdx.x;            // blockDim = 256 = DIM
    float v = (x[b * DIM + d] - mean[d]) * inv_std[d];
    float s = v * v;
    #pragma unroll
    for (int o = 16; o; o >>= 1) s += __shfl_xor_sync(0xffffffffu, s, o);
    __shared__ float ws[8];
    int w = threadIdx.x >> 5, l = threadIdx.x & 31;
    if (l == 0) ws[w] = s;
    __syncthreads();
    if (threadIdx.x == 0) {
        float t = 0.f;
        #pragma unroll
        for (int i = 0; i < 8; i++) t += ws[i];
        ws[0] = t;
    }
    __syncthreads();
    float outv = v / fmaxf(sqrtf(ws[0]), EPSF);
    g_qn[b * DIM + d] = outv;
    g_qb[b * DIM + d] = __float2bfloat16(outv);
}

// ---------------------------------------------------------------------------
// Kernel 2: bf16 pre-normalized train bank + fp32 inverse norms (one warp/row)
// ---------------------------------------------------------------------------
__global__ void tconv_kernel(const float* __restrict__ tx) {
    int gw   = (blockIdx.x * blockDim.x + threadIdx.x) >> 5;
    int lane = threadIdx.x & 31;
    if (gw >= NPAD) return;
    uint4* dst = (uint4*)(g_tb + (size_t)gw * DIM) + lane;   // 8 bf16 per lane
    if (gw >= NTRAIN) {
        uint4 z; z.x = z.y = z.z = z.w = 0u;
        *dst = z;
        if (lane == 0) g_tinv[gw] = 0.f;
        return;
    }
    const float4* row = (const float4*)(tx + (size_t)gw * DIM);
    float4 a = row[lane * 2];
    float4 b = row[lane * 2 + 1];
    float s = a.x*a.x + a.y*a.y + a.z*a.z + a.w*a.w
            + b.x*b.x + b.y*b.y + b.z*b.z + b.w*b.w;
    #pragma unroll
    for (int o = 16; o; o >>= 1) s += __shfl_xor_sync(0xffffffffu, s, o);
    float inv = 1.f / fmaxf(sqrtf(s), EPSF);
    __nv_bfloat162 p0 = __floats2bfloat162_rn(a.x * inv, a.y * inv);
    __nv_bfloat162 p1 = __floats2bfloat162_rn(a.z * inv, a.w * inv);
    __nv_bfloat162 p2 = __floats2bfloat162_rn(b.x * inv, b.y * inv);
    __nv_bfloat162 p3 = __floats2bfloat162_rn(b.z * inv, b.w * inv);
    uint4 o4;
    o4.x = *(uint32_t*)&p0; o4.y = *(uint32_t*)&p1;
    o4.z = *(uint32_t*)&p2; o4.w = *(uint32_t*)&p3;
    *dst = o4;
    if (lane == 0) g_tinv[gw] = inv;
}

// ---------------------------------------------------------------------------
// B slab loader: 128 rows x 128 bf16 (256B/row, 16 chunks), xor-swizzled
//   512 threads: 4 chunks per thread
// ---------------------------------------------------------------------------
__device__ __forceinline__ void load_slab(uint32_t smdst,
                                          const __nv_bfloat16* src_base, int tid) {
    #pragma unroll
    for (int k = 0; k < 4; k++) {
        int l = tid + k * NTHREADS;
        int row = l >> 4, c = l & 15;
        uint32_t dst = smdst + (uint32_t)row * 256u
                     + (uint32_t)((c ^ (row & 7)) * 16);
        cp16(dst, (const char*)(src_base + (size_t)row * DIM) + c * 16);
    }
}

// Fragment fetch for one k-step (kk within slab h)
__device__ __forceinline__ void load_frags(uint32_t smb, uint32_t bbase,
                                           const int* aRow, const int* bRow,
                                           int aHalf, int bHalf, int h, int kk,
                                           uint32_t af[2][4], uint32_t bf[2][4]) {
    int cA = (h * 8 + kk) * 2 + aHalf;
    #pragma unroll
    for (int i = 0; i < 2; i++) {
        uint32_t ad = smb + OFF_A + (uint32_t)aRow[i] * 512u
                    + (uint32_t)(((cA ^ (aRow[i] & 7))) * 16);
        ldsm_x4(ad, af[i][0], af[i][1], af[i][2], af[i][3]);
    }
    int cB = kk * 2 + bHalf;
    #pragma unroll
    for (int j2 = 0; j2 < 2; j2++) {
        uint32_t bd = bbase + (uint32_t)bRow[j2] * 256u
                    + (uint32_t)(((cB ^ (bRow[j2] & 7))) * 16);
        ldsm_x4(bd, bf[j2][0], bf[j2][1], bf[j2][2], bf[j2][3]);
    }
}

// ---------------------------------------------------------------------------
// Kernel 3: warp-MMA bf16 GEMM (128x128xK256 per tile) + fused per-chunk top-20
//   grid = (NCHUNKS, QTILES), block = 512 (16 warps, 4M x 4N), 1 CTA/SM
// ---------------------------------------------------------------------------
__global__ __launch_bounds__(NTHREADS, 1)
void knn_main() {
    extern __shared__ char sm[];
    uint32_t smb = smem_u32(sm);
    const int tid  = threadIdx.x;
    const int wid  = tid >> 5, lane = tid & 31;
    const int wm = wid >> 2, wn = wid & 3;          // warp grid 4 x 4
    const int qtile = blockIdx.y, chunk = blockIdx.x;
    const int tbase0 = chunk * CHUNK;

    float* sims = (float*)(sm + OFF_SIMS);
    float* topv = (float*)(sm + OFF_TOPV);
    int*   topi = (int*)  (sm + OFF_TOPI);

    for (int l = tid; l < 128 * KSEL; l += NTHREADS)
        topv[(l / KSEL) * 21 + (l % KSEL)] = -1e30f;

    // Prologue: A tile (queries, 8 chunks/thread) + B slabs 0,1
    {
        const __nv_bfloat16* asrc = g_qb + (size_t)qtile * 128 * DIM;
        #pragma unroll
        for (int k = 0; k < 8; k++) {
            int l = tid + k * NTHREADS;
            int row = l >> 5, c = l & 31;
            uint32_t dst = smb + OFF_A + (uint32_t)row * 512u
                         + (uint32_t)((c ^ (row & 7)) * 16);
            cp16(dst, (const char*)(asrc + (size_t)row * DIM) + c * 16);
        }
        load_slab(smb + OFF_B0, g_tb + (size_t)tbase0 * DIM, tid);
        CP_COMMIT();
        load_slab(smb + OFF_B1, g_tb + (size_t)tbase0 * DIM + 128, tid);
        CP_COMMIT();
    }

    // per-thread fragment row bases (warp tile 32M x 32N)
    int aRow[2], bRow[2];
    #pragma unroll
    for (int i = 0; i < 2; i++) aRow[i] = wm * 32 + i * 16 + (lane & 15);
    #pragma unroll
    for (int j2 = 0; j2 < 2; j2++)
        bRow[j2] = wn * 32 + j2 * 16 + (lane & 7) + ((lane & 16) >> 1);
    const int aHalf = lane >> 4;         // A: k-half chunk offset
    const int bHalf = (lane >> 3) & 1;   // B: k-half chunk offset

    float minv = -1e30f; int minp = 0;

    for (int t = 0; t < TILES_PC; t++) {
        float acc[2][4][4];
        #pragma unroll
        for (int i = 0; i < 2; i++)
            #pragma unroll
            for (int j = 0; j < 4; j++)
                #pragma unroll
                for (int e = 0; e < 4; e++) acc[i][j][e] = 0.f;

        #pragma unroll
        for (int h = 0; h < 2; h++) {
            CP_WAIT1();
            __syncthreads();           // slab (2t+h) resident in buf[h]
            uint32_t bbase = smb + (h ? OFF_B1 : OFF_B0);

            // software-pipelined k-loop: frags for kk+1 issued before MMAs of kk
            uint32_t af[2][2][4], bf[2][2][4];
            load_frags(smb, bbase, aRow, bRow, aHalf, bHalf, h, 0, af[0], bf[0]);
            #pragma unroll
            for (int kk = 0; kk < 8; kk++) {
                int cur = kk & 1;
                if (kk < 7)
                    load_frags(smb, bbase, aRow, bRow, aHalf, bHalf, h, kk + 1,
                               af[cur ^ 1], bf[cur ^ 1]);
                #pragma unroll
                for (int i = 0; i < 2; i++)
                    #pragma unroll
                    for (int j = 0; j < 4; j++)
                        mma16816(acc[i][j], af[cur][i],
                                 bf[cur][j >> 1][(j & 1) * 2],
                                 bf[cur][j >> 1][(j & 1) * 2 + 1]);
            }
            __syncthreads();           // all warps done reading buf[h]
            int s = 2 * t + h;
            if (s + 2 < NSLABS) {
                int tile2 = (s + 2) >> 1, h2 = (s + 2) & 1;
                load_slab(smb + (h2 ? OFF_B1 : OFF_B0),
                          g_tb + (size_t)(tbase0 + tile2 * 128) * DIM + h2 * 128, tid);
            }
            CP_COMMIT();               // keep group count aligned
        }

        // epilogue: stage sims, then per-query top-20 scan
        #pragma unroll
        for (int i = 0; i < 2; i++) {
            int r0 = wm * 32 + i * 16 + (lane >> 2);
            #pragma unroll
            for (int j = 0; j < 4; j++) {
                int c0 = wn * 32 + j * 8 + 2 * (lane & 3);
                *(float2*)&sims[r0 * SIMS_PITCH + c0] =
                    make_float2(acc[i][j][0], acc[i][j][1]);
                *(float2*)&sims[(r0 + 8) * SIMS_PITCH + c0] =
                    make_float2(acc[i][j][2], acc[i][j][3]);
            }
        }
        __syncthreads();
        if (tid < 128) {
            int tbase = tbase0 + t * 128;
            int lim = min(128, NTRAIN - tbase);
            const float* srow = sims + tid * SIMS_PITCH;
            float* tvq = topv + tid * 21;
            int*   tiq = topi + tid * 21;
            for (int j = 0; j < lim; j++) {
                float v = srow[j];
                if (v > minv) {
                    tvq[minp] = v; tiq[minp] = tbase + j;
                    minv = tvq[0]; minp = 0;
                    #pragma unroll
                    for (int m = 1; m < KSEL; m++) {
                        float t2 = tvq[m];
                        if (t2 < minv) { minv = t2; minp = m; }
                    }
                }
            }
        }
        __syncthreads();
    }

    if (tid < 128) {
        int q = qtile * 128 + tid;
        size_t base = ((size_t)q * NCHUNKS + chunk) * KSEL;
        #pragma unroll
        for (int j = 0; j < KSEL; j++) {
            g_pvals[base + j] = topv[tid * 21 + j];
            g_pidx [base + j] = topi[tid * 21 + j];
        }
    }
}

// ---------------------------------------------------------------------------
// Kernel 4: top-32 bf16 candidates -> fp32 rescore -> top-20 -> softmax/scatter
//   grid = BQ, block = 256
// ---------------------------------------------------------------------------
__global__ __launch_bounds__(256)
void knn_merge(const float* __restrict__ train, const void* __restrict__ ty_raw,
               float* __restrict__ out) {
    __shared__ float vals[NCANDTOT];
    __shared__ int   idxs[NCANDTOT];
    __shared__ __align__(16) float qs[DIM];
    __shared__ int   seli[KCAND];
    __shared__ float rsc[KCAND];
    __shared__ float s2v[KSEL];
    __shared__ int   s2i[KSEL];
    __shared__ float rv[8];
    __shared__ int   rp[8];

    int q = blockIdx.x, tid = threadIdx.x;
    for (int l = tid; l < NCANDTOT; l += 256) {
        vals[l] = g_pvals[(size_t)q * NCANDTOT + l];
        idxs[l] = g_pidx [(size_t)q * NCANDTOT + l];
    }
    qs[tid] = g_qn[(size_t)q * DIM + tid];
    for (int c = tid; c < NCLASS; c += 256) out[(size_t)q * NCLASS + c] = 0.f;
    __syncthreads();

    // register-local maxima: thread owns candidates tid + k*256
    float lmax = -INFINITY; int lpos = tid;
    for (int l = tid; l < NCANDTOT; l += 256) {
        float v = vals[l];
        if (v > lmax) { lmax = v; lpos = l; }
    }

    // iterative top-KCAND selection (winner-only rescan)
    for (int it = 0; it < KCAND; it++) {
        float bv = lmax; int bt = tid;
        #pragma unroll
        for (int o = 16; o; o >>= 1) {
            float ov = __shfl_xor_sync(0xffffffffu, bv, o);
            int   ot = __shfl_xor_sync(0xffffffffu, bt, o);
            if (ov > bv || (ov == bv && ot < bt)) { bv = ov; bt = ot; }
        }
        if ((tid & 31) == 0) { rv[tid >> 5] = bv; rp[tid >> 5] = bt; }
        __syncthreads();
        float fb = rv[0]; int ft = rp[0];
        #pragma unroll
        for (int i = 1; i < 8; i++)
            if (rv[i] > fb || (rv[i] == fb && rp[i] < ft)) { fb = rv[i]; ft = rp[i]; }
        if (tid == ft) {
            seli[it] = idxs[lpos];
            vals[lpos] = -INFINITY;
            lmax = -INFINITY; lpos = tid;
            for (int l = tid; l < NCANDTOT; l += 256) {
                float v = vals[l];
                if (v > lmax) { lmax = v; lpos = l; }
            }
        }
        __syncthreads();
    }

    // exact fp32 rescore: 8 threads per candidate, 32 dims each
    {
        int c = tid >> 3, seg = tid & 7;
        const float4* tr = (const float4*)(train + (size_t)seli[c] * DIM + seg * 32);
        const float4* qq = (const float4*)(qs + seg * 32);
        float s = 0.f;
        #pragma unroll
        for (int i = 0; i < 8; i++) {
            float4 tv = tr[i]; float4 qv = qq[i];
            s += tv.x * qv.x + tv.y * qv.y + tv.z * qv.z + tv.w * qv.w;
        }
        #pragma unroll
        for (int o = 4; o; o >>= 1) s += __shfl_down_sync(0xffffffffu, s, o, 8);
        if (seg == 0) rsc[c] = s * g_tinv[seli[c]];
    }
    __syncthreads();

    // exact top-20 of the 32 rescored candidates (warp 0)
    if (tid < 32) {
        float mv = rsc[tid];
        for (int it = 0; it < KSEL; it++) {
            float bv = mv; int bl = tid;
            #pragma unroll
            for (int o = 16; o; o >>= 1) {
                float ov = __shfl_xor_sync(0xffffffffu, bv, o);
                int   ol = __shfl_xor_sync(0xffffffffu, bl, o);
                if (ov > bv || (ov == bv && ol < bl)) { bv = ov; bl = ol; }
            }
            if (tid == 0) { s2v[it] = bv; s2i[it] = seli[bl]; }
            if (tid == bl) mv = -INFINITY;
        }
        __syncwarp();
    }
    __syncthreads();

    if (tid == 0) {
        // detect int64 vs int32 labels (labels < 1000 -> zero high words)
        const int* y32 = (const int*)ty_raw;
        bool is64 = true;
        #pragma unroll
        for (int i = 1; i < 32; i += 2) is64 = is64 && (y32[i] == 0);

        float m0 = s2v[0], s = 0.f;
        float w20[KSEL];
        #pragma unroll
        for (int j = 0; j < KSEL; j++) {
            float w = expf((s2v[j] - m0) * TEMPF);
            w20[j] = w; s += w;
        }
        float inv = 1.f / s;
        for (int j = 0; j < KSEL; j++) {
            int id  = s2i[j];
            int lab = is64 ? (int)((const long long*)ty_raw)[id] : y32[id];
            out[(size_t)q * NCLASS + lab] += w20[j] * inv;
        }
    }
}

// ---------------------------------------------------------------------------
extern "C" void kernel_launch(void* const* d_in, const int* in_sizes, int n_in,
                              void* d_out, int out_size) {
    const float* x       = (const float*)d_in[0];
    const float* mean    = (const float*)d_in[1];
    const float* inv_std = (const float*)d_in[2];
    const float* train_x = (const float*)d_in[3];
    const void*  train_y = d_in[4];
    float* out = (float*)d_out;

    qnorm_kernel<<<BQ, 256>>>(x, mean, inv_std);
    tconv_kernel<<<NPAD / 8, 256>>>(train_x);          // 1 warp per row

    cudaFuncSetAttribute(knn_main, cudaFuncAttributeMaxDynamicSharedMemorySize, SMEM_TOT);
    knn_main<<<dim3(NCHUNKS, QTILES), NTHREADS, SMEM_TOT>>>();

    knn_merge<<<BQ, 256>>>(train_x, train_y, out);
}

// round 14
// speedup vs baseline: 1.4540x; 1.0230x over previous
#include <cuda_runtime.h>
#include <cuda_fp16.h>
#include <math.h>
#include <stdint.h>

// Problem constants
#define BQ      1024
#define DIM     256
#define NTRAIN  200000
#define NCLASS  1000
#define KSEL    20
#define KCAND   32          // f16 candidates kept for fp32 rescoring
#define TEMPF   20.0f
#define EPSF    1e-8f

// Tiling
#define CHUNK    2048
#define NCHUNKS  98
#define NPAD     (NCHUNKS*CHUNK)     // 200704 padded train rows
#define QTILES   8
#define NCANDTOT (NCHUNKS*KSEL)      // 1960 candidates/query
#define TILES_PC 16                  // 128-row tiles per chunk
#define NSLABS   32                  // 2 K-slabs per tile

// knn_main dynamic smem layout (bytes)
#define OFF_A    0u                  // A: 128 rows x 512B (256 f16)   = 65536
#define OFF_B0   65536u              // B slab: 128 rows x 256B (128 f16) = 32768
#define OFF_B1   98304u
#define OFF_SIMS 131072u             // 128 x 130 fp32 = 66560
#define OFF_TOPV 197632u             // 128 x 21 fp32  = 10752
#define OFF_TOPI 208384u             // 128 x 21 int   = 10752
#define SMEM_TOT 219136u
#define SIMS_PITCH 130

// Scratch (__device__ globals; no allocations allowed)
__device__ float   g_qn[BQ * DIM];            // fp32 normalized queries
__device__ __half  g_qh[BQ * DIM];            // f16 normalized queries
__device__ __half  g_th[(size_t)NPAD * DIM];  // f16 pre-normalized train bank
__device__ float   g_tinv[NPAD];              // 1/max(||t||,eps)
__device__ float g_pvals[(size_t)BQ * NCHUNKS * KSEL];
__device__ int   g_pidx [(size_t)BQ * NCHUNKS * KSEL];

// ---------------------------------------------------------------------------
// Plain-PTX helpers (valid on base sm_103 target: no "a"-only features)
// ---------------------------------------------------------------------------
__device__ __forceinline__ uint32_t smem_u32(const void* p) {
    uint32_t a;
    asm("{ .reg .u64 t; cvta.to.shared.u64 t, %1; cvt.u32.u64 %0, t; }"
        : "=r"(a) : "l"(p));
    return a;
}
__device__ __forceinline__ void cp16(uint32_t dst, const void* src) {
    asm volatile("cp.async.cg.shared.global [%0], [%1], 16;"
                 :: "r"(dst), "l"(src));
}
#define CP_COMMIT() asm volatile("cp.async.commit_group;" ::: "memory")
#define CP_WAIT1()  asm volatile("cp.async.wait_group 1;" ::: "memory")

__device__ __forceinline__ void ldsm_x4(uint32_t addr, uint32_t& r0, uint32_t& r1,
                                        uint32_t& r2, uint32_t& r3) {
    asm volatile("ldmatrix.sync.aligned.m8n8.x4.shared.b16 {%0,%1,%2,%3}, [%4];"
                 : "=r"(r0), "=r"(r1), "=r"(r2), "=r"(r3) : "r"(addr));
}
// f16 MMA with f16 accumulate (2 D regs = 4 halves)
__device__ __forceinline__ void mma16816h(uint32_t* d, const uint32_t* a,
                                          uint32_t b0, uint32_t b1) {
    asm volatile("mma.sync.aligned.m16n8k16.row.col.f16.f16.f16.f16 "
                 "{%0,%1}, {%2,%3,%4,%5}, {%6,%7}, {%0,%1};"
                 : "+r"(d[0]), "+r"(d[1])
                 : "r"(a[0]), "r"(a[1]), "r"(a[2]), "r"(a[3]), "r"(b0), "r"(b1));
}

// ---------------------------------------------------------------------------
// Kernel 1: q = normalize((x - mean) * inv_std)  -> fp32 + f16
// ---------------------------------------------------------------------------
__global__ void qnorm_kernel(const float* __restrict__ x,
                             const float* __restrict__ mean,
                             const float* __restrict__ inv_std) {
    int b = blockIdx.x;
    int d = threadIdx.x;            // blockDim = 256 = DIM
    float v = (x[b * DIM + d] - mean[d]) * inv_std[d];
    float s = v * v;
    #pragma unroll
    for (int o = 16; o; o >>= 1) s += __shfl_xor_sync(0xffffffffu, s, o);
    __shared__ float ws[8];
    int w = threadIdx.x >> 5, l = threadIdx.x & 31;
    if (l == 0) ws[w] = s;
    __syncthreads();
    if (threadIdx.x == 0) {
        float t = 0.f;
        #pragma unroll
        for (int i = 0; i < 8; i++) t += ws[i];
        ws[0] = t;
    }
    __syncthreads();
    float outv = v / fmaxf(sqrtf(ws[0]), EPSF);
    g_qn[b * DIM + d] = outv;
    g_qh[b * DIM + d] = __float2half(outv);
}

// ---------------------------------------------------------------------------
// Kernel 2: f16 pre-normalized train bank + fp32 inverse norms (one warp/row)
// ---------------------------------------------------------------------------
__global__ void tconv_kernel(const float* __restrict__ tx) {
    int gw   = (blockIdx.x * blockDim.x + threadIdx.x) >> 5;
    int lane = threadIdx.x & 31;
    if (gw >= NPAD) return;
    uint4* dst = (uint4*)(g_th + (size_t)gw * DIM) + lane;   // 8 f16 per lane
    if (gw >= NTRAIN) {
        uint4 z; z.x = z.y = z.z = z.w = 0u;
        *dst = z;
        if (lane == 0) g_tinv[gw] = 0.f;
        return;
    }
    const float4* row = (const float4*)(tx + (size_t)gw * DIM);
    float4 a = row[lane * 2];
    float4 b = row[lane * 2 + 1];
    float s = a.x*a.x + a.y*a.y + a.z*a.z + a.w*a.w
            + b.x*b.x + b.y*b.y + b.z*b.z + b.w*b.w;
    #pragma unroll
    for (int o = 16; o; o >>= 1) s += __shfl_xor_sync(0xffffffffu, s, o);
    float inv = 1.f / fmaxf(sqrtf(s), EPSF);
    __half2 p0 = __floats2half2_rn(a.x * inv, a.y * inv);
    __half2 p1 = __floats2half2_rn(a.z * inv, a.w * inv);
    __half2 p2 = __floats2half2_rn(b.x * inv, b.y * inv);
    __half2 p3 = __floats2half2_rn(b.z * inv, b.w * inv);
    uint4 o4;
    o4.x = *(uint32_t*)&p0; o4.y = *(uint32_t*)&p1;
    o4.z = *(uint32_t*)&p2; o4.w = *(uint32_t*)&p3;
    *dst = o4;
    if (lane == 0) g_tinv[gw] = inv;
}

// ---------------------------------------------------------------------------
// B slab loader: 128 rows x 128 f16 (256B/row, 16 chunks), xor-swizzled
// ---------------------------------------------------------------------------
__device__ __forceinline__ void load_slab(uint32_t smdst,
                                          const __half* src_base, int tid) {
    #pragma unroll
    for (int k = 0; k < 8; k++) {
        int l = tid + k * 256;
        int row = l >> 4, c = l & 15;
        uint32_t dst = smdst + (uint32_t)row * 256u
                     + (uint32_t)((c ^ (row & 7)) * 16);
        cp16(dst, (const char*)(src_base + (size_t)row * DIM) + c * 16);
    }
}

// ---------------------------------------------------------------------------
// Kernel 3: warp-MMA f16 GEMM (128x128xK256 per tile) + fused per-chunk top-20
//   grid = (NCHUNKS, QTILES), block = 256 (8 warps, 2M x 4N), 1 CTA/SM
// ---------------------------------------------------------------------------
__global__ __launch_bounds__(256, 1)
void knn_main() {
    extern __shared__ char sm[];
    uint32_t smb = smem_u32(sm);
    const int tid  = threadIdx.x;
    const int wid  = tid >> 5, lane = tid & 31;
    const int wm = wid >> 2, wn = wid & 3;          // warp grid 2 x 4
    const int qtile = blockIdx.y, chunk = blockIdx.x;
    const int tbase0 = chunk * CHUNK;

    float* sims = (float*)(sm + OFF_SIMS);
    float* topv = (float*)(sm + OFF_TOPV);
    int*   topi = (int*)  (sm + OFF_TOPI);

    // init top-k lists
    for (int l = tid; l < 128 * KSEL; l += 256)
        topv[(l / KSEL) * 21 + (l % KSEL)] = -1e30f;

    // Prologue: A tile (queries, 16 chunks/thread) + B slabs 0,1
    {
        const __half* asrc = g_qh + (size_t)qtile * 128 * DIM;
        #pragma unroll
        for (int k = 0; k < 16; k++) {
            int l = tid + k * 256;
            int row = l >> 5, c = l & 31;
            uint32_t dst = smb + OFF_A + (uint32_t)row * 512u
                         + (uint32_t)((c ^ (row & 7)) * 16);
            cp16(dst, (const char*)(asrc + (size_t)row * DIM) + c * 16);
        }
        load_slab(smb + OFF_B0, g_th + (size_t)tbase0 * DIM, tid);
        CP_COMMIT();
        load_slab(smb + OFF_B1, g_th + (size_t)tbase0 * DIM + 128, tid);
        CP_COMMIT();
    }

    // per-thread fragment row bases
    int aRow[4], bRow[2];
    #pragma unroll
    for (int i = 0; i < 4; i++) aRow[i] = wm * 64 + i * 16 + (lane & 15);
    #pragma unroll
    for (int j2 = 0; j2 < 2; j2++)
        bRow[j2] = wn * 32 + j2 * 16 + (lane & 7) + ((lane & 16) >> 1);
    const int aHalf = lane >> 4;         // A: k-half chunk offset
    const int bHalf = (lane >> 3) & 1;   // B: k-half chunk offset

    float minv = -1e30f; int minp = 0;

    for (int t = 0; t < TILES_PC; t++) {
        uint32_t acc[4][4][2];           // f16x2 accumulators
        #pragma unroll
        for (int i = 0; i < 4; i++)
            #pragma unroll
            for (int j = 0; j < 4; j++) { acc[i][j][0] = 0u; acc[i][j][1] = 0u; }

        #pragma unroll
        for (int h = 0; h < 2; h++) {
            CP_WAIT1();
            __syncthreads();           // slab (2t+h) resident in buf[h]
            uint32_t bbase = smb + (h ? OFF_B1 : OFF_B0);
            #pragma unroll
            for (int kk = 0; kk < 8; kk++) {
                uint32_t a[4][4];
                int cA = (h * 8 + kk) * 2 + aHalf;
                #pragma unroll
                for (int i = 0; i < 4; i++) {
                    uint32_t ad = smb + OFF_A + (uint32_t)aRow[i] * 512u
                                + (uint32_t)(((cA ^ (aRow[i] & 7))) * 16);
                    ldsm_x4(ad, a[i][0], a[i][1], a[i][2], a[i][3]);
                }
                uint32_t b[2][4];
                int cB = kk * 2 + bHalf;
                #pragma unroll
                for (int j2 = 0; j2 < 2; j2++) {
                    uint32_t bd = bbase + (uint32_t)bRow[j2] * 256u
                                + (uint32_t)(((cB ^ (bRow[j2] & 7))) * 16);
                    ldsm_x4(bd, b[j2][0], b[j2][1], b[j2][2], b[j2][3]);
                }
                #pragma unroll
                for (int i = 0; i < 4; i++)
                    #pragma unroll
                    for (int j = 0; j < 4; j++)
                        mma16816h(acc[i][j], a[i],
                                  b[j >> 1][(j & 1) * 2], b[j >> 1][(j & 1) * 2 + 1]);
            }
            __syncthreads();           // all warps done reading buf[h]
            int s = 2 * t + h;
            if (s + 2 < NSLABS) {
                int tile2 = (s + 2) >> 1, h2 = (s + 2) & 1;
                load_slab(smb + (h2 ? OFF_B1 : OFF_B0),
                          g_th + (size_t)(tbase0 + tile2 * 128) * DIM + h2 * 128, tid);
            }
            CP_COMMIT();               // keep group count aligned
        }

        // epilogue: unpack f16 accs to fp32 sims, then per-query top-20 scan
        #pragma unroll
        for (int i = 0; i < 4; i++) {
            int r0 = wm * 64 + i * 16 + (lane >> 2);
            #pragma unroll
            for (int j = 0; j < 4; j++) {
                int c0 = wn * 32 + j * 8 + 2 * (lane & 3);
                float2 f0 = __half22float2(*(__half2*)&acc[i][j][0]);
                float2 f1 = __half22float2(*(__half2*)&acc[i][j][1]);
                *(float2*)&sims[r0 * SIMS_PITCH + c0] = f0;
                *(float2*)&sims[(r0 + 8) * SIMS_PITCH + c0] = f1;
            }
        }
        __syncthreads();
        if (tid < 128) {
            int tbase = tbase0 + t * 128;
            int lim = min(128, NTRAIN - tbase);
            const float* srow = sims + tid * SIMS_PITCH;
            float* tvq = topv + tid * 21;
            int*   tiq = topi + tid * 21;
            for (int j = 0; j < lim; j++) {
                float v = srow[j];
                if (v > minv) {
                    tvq[minp] = v; tiq[minp] = tbase + j;
                    minv = tvq[0]; minp = 0;
                    #pragma unroll
                    for (int m = 1; m < KSEL; m++) {
                        float t2 = tvq[m];
                        if (t2 < minv) { minv = t2; minp = m; }
                    }
                }
            }
        }
        __syncthreads();
    }

    if (tid < 128) {
        int q = qtile * 128 + tid;
        size_t base = ((size_t)q * NCHUNKS + chunk) * KSEL;
        #pragma unroll
        for (int j = 0; j < KSEL; j++) {
            g_pvals[base + j] = topv[tid * 21 + j];
            g_pidx [base + j] = topi[tid * 21 + j];
        }
    }
}

// ---------------------------------------------------------------------------
// Kernel 4: top-32 f16 candidates -> fp32 rescore -> top-20 -> softmax/scatter
//   grid = BQ, block = 256
// ---------------------------------------------------------------------------
__global__ __launch_bounds__(256)
void knn_merge(const float* __restrict__ train, const void* __restrict__ ty_raw,
               float* __restrict__ out) {
    __shared__ float vals[NCANDTOT];
    __shared__ int   idxs[NCANDTOT];
    __shared__ __align__(16) float qs[DIM];
    __shared__ int   seli[KCAND];
    __shared__ float rsc[KCAND];
    __shared__ float s2v[KSEL];
    __shared__ int   s2i[KSEL];
    __shared__ float rv[8];
    __shared__ int   rp[8];

    int q = blockIdx.x, tid = threadIdx.x;
    for (int l = tid; l < NCANDTOT; l += 256) {
        vals[l] = g_pvals[(size_t)q * NCANDTOT + l];
        idxs[l] = g_pidx [(size_t)q * NCANDTOT + l];
    }
    qs[tid] = g_qn[(size_t)q * DIM + tid];
    for (int c = tid; c < NCLASS; c += 256) out[(size_t)q * NCLASS + c] = 0.f;
    __syncthreads();

    // register-local maxima: thread owns candidates tid + k*256
    float lmax = -INFINITY; int lpos = tid;
    for (int l = tid; l < NCANDTOT; l += 256) {
        float v = vals[l];
        if (v > lmax) { lmax = v; lpos = l; }
    }

    // iterative top-KCAND selection (winner-only rescan)
    for (int it = 0; it < KCAND; it++) {
        float bv = lmax; int bt = tid;
        #pragma unroll
        for (int o = 16; o; o >>= 1) {
            float ov = __shfl_xor_sync(0xffffffffu, bv, o);
            int   ot = __shfl_xor_sync(0xffffffffu, bt, o);
            if (ov > bv || (ov == bv && ot < bt)) { bv = ov; bt = ot; }
        }
        if ((tid & 31) == 0) { rv[tid >> 5] = bv; rp[tid >> 5] = bt; }
        __syncthreads();
        float fb = rv[0]; int ft = rp[0];
        #pragma unroll
        for (int i = 1; i < 8; i++)
            if (rv[i] > fb || (rv[i] == fb && rp[i] < ft)) { fb = rv[i]; ft = rp[i]; }
        if (tid == ft) {
            seli[it] = idxs[lpos];
            vals[lpos] = -INFINITY;
            lmax = -INFINITY; lpos = tid;
            for (int l = tid; l < NCANDTOT; l += 256) {
                float v = vals[l];
                if (v > lmax) { lmax = v; lpos = l; }
            }
        }
        __syncthreads();
    }

    // exact fp32 rescore: 8 threads per candidate, 32 dims each
    {
        int c = tid >> 3, seg = tid & 7;
        const float4* tr = (const float4*)(train + (size_t)seli[c] * DIM + seg * 32);
        const float4* qq = (const float4*)(qs + seg * 32);
        float s = 0.f;
        #pragma unroll
        for (int i = 0; i < 8; i++) {
            float4 tv = tr[i]; float4 qv = qq[i];
            s += tv.x * qv.x + tv.y * qv.y + tv.z * qv.z + tv.w * qv.w;
        }
        #pragma unroll
        for (int o = 4; o; o >>= 1) s += __shfl_down_sync(0xffffffffu, s, o, 8);
        if (seg == 0) rsc[c] = s * g_tinv[seli[c]];
    }
    __syncthreads();

    // exact top-20 of the 32 rescored candidates (warp 0)
    if (tid < 32) {
        float mv = rsc[tid];
        for (int it = 0; it < KSEL; it++) {
            float bv = mv; int bl = tid;
            #pragma unroll
            for (int o = 16; o; o >>= 1) {
                float ov = __shfl_xor_sync(0xffffffffu, bv, o);
                int   ol = __shfl_xor_sync(0xffffffffu, bl, o);
                if (ov > bv || (ov == bv && ol < bl)) { bv = ov; bl = ol; }
            }
            if (tid == 0) { s2v[it] = bv; s2i[it] = seli[bl]; }
            if (tid == bl) mv = -INFINITY;
        }
        __syncwarp();
    }
    __syncthreads();

    if (tid == 0) {
        // detect int64 vs int32 labels (labels < 1000 -> zero high words)
        const int* y32 = (const int*)ty_raw;
        bool is64 = true;
        #pragma unroll
        for (int i = 1; i < 32; i += 2) is64 = is64 && (y32[i] == 0);

        float m0 = s2v[0], s = 0.f;
        float w20[KSEL];
        #pragma unroll
        for (int j = 0; j < KSEL; j++) {
            float w = expf((s2v[j] - m0) * TEMPF);
            w20[j] = w; s += w;
        }
        float inv = 1.f / s;
        for (int j = 0; j < KSEL; j++) {
            int id  = s2i[j];
            int lab = is64 ? (int)((const long long*)ty_raw)[id] : y32[id];
            out[(size_t)q * NCLASS + lab] += w20[j] * inv;
        }
    }
}

// ---------------------------------------------------------------------------
extern "C" void kernel_launch(void* const* d_in, const int* in_sizes, int n_in,
                              void* d_out, int out_size) {
    const float* x       = (const float*)d_in[0];
    const float* mean    = (const float*)d_in[1];
    const float* inv_std = (const float*)d_in[2];
    const float* train_x = (const float*)d_in[3];
    const void*  train_y = d_in[4];
    float* out = (float*)d_out;

    qnorm_kernel<<<BQ, 256>>>(x, mean, inv_std);
    tconv_kernel<<<NPAD / 8, 256>>>(train_x);          // 1 warp per row

    cudaFuncSetAttribute(knn_main, cudaFuncAttributeMaxDynamicSharedMemorySize, SMEM_TOT);
    knn_main<<<dim3(NCHUNKS, QTILES), 256, SMEM_TOT>>>();

    knn_merge<<<BQ, 256>>>(train_x, train_y, out);
}